// round 6
// baseline (speedup 1.0000x reference)
#include <cuda_runtime.h>
#include <cuda_fp16.h>

// Fixed problem shape (SimpleGNN): N=100000 nodes, E=1600000 edges, dims 64->64->64
#define MAXN 100000
#define MAXE 1600000

// Scratch (device globals -- no runtime allocation allowed)
__device__ __half g_hbuf[MAXN * 64];   // fp16 pre-scaled message table
__device__ float  g_bufB[MAXN * 64];   // fp32 hidden activations
__device__ int    g_indeg[MAXN];       // zeroed in k_scan after use (replay invariant)
__device__ int    g_offs[MAXN];        // exclusive offsets; shifted to ends by k_fill
__device__ int    g_csr[MAXE];         // src index only (weight folded into message)
__device__ float  g_dinv[MAXN];
__device__ unsigned long long g_state[128];  // lookback: (flag<<32)|value, reset each call
__device__ int    g_done;

// ---------------------------------------------------------------------------
// f32x2 packed-FMA helpers (sm_10x FFMA2 -- only reachable via PTX)
// ---------------------------------------------------------------------------
__device__ __forceinline__ void ffma2(unsigned long long& acc,
                                      unsigned long long a, unsigned long long b) {
    asm("fma.rn.f32x2 %0, %1, %2, %0;" : "+l"(acc) : "l"(a), "l"(b));
}
__device__ __forceinline__ unsigned long long pack2(float v) {
    unsigned long long r;
    asm("mov.b64 %0, {%1, %1};" : "=l"(r) : "f"(v));
    return r;
}
__device__ __forceinline__ float2 unpack2(unsigned long long v) {
    float2 r;
    asm("mov.b64 {%0, %1}, %2;" : "=f"(r.x), "=f"(r.y) : "l"(v));
    return r;
}
__device__ __forceinline__ unsigned h2_bits(__half2 h) {
    return *reinterpret_cast<unsigned*>(&h);
}

// ---------------------------------------------------------------------------
// Histogram of in-degrees
// ---------------------------------------------------------------------------
__global__ void k_hist(const int4* __restrict__ dst4, int E4, const int* __restrict__ dst, int E) {
    int i = blockIdx.x * blockDim.x + threadIdx.x;
    if (i < E4) {
        int4 d = __ldg(&dst4[i]);
        atomicAdd(&g_indeg[d.x], 1);
        atomicAdd(&g_indeg[d.y], 1);
        atomicAdd(&g_indeg[d.z], 1);
        atomicAdd(&g_indeg[d.w], 1);
    }
    int t = E4 * 4 + i;
    if (i < (E & 3) && t < E) atomicAdd(&g_indeg[dst[t]], 1);
}

// ---------------------------------------------------------------------------
// Single-pass scan (decoupled lookback). One launch computes:
//   g_offs[i] = exclusive prefix of indeg, g_dinv[i] = rsqrt(indeg+1),
//   g_indeg[i] = 0 (ready for next replay).
// Grid = ceil(n/1024) = 98 blocks <= 148 SMs -> all resident, lookback safe.
// Last-finishing block resets g_state/g_done so each replay starts clean.
// ---------------------------------------------------------------------------
__global__ __launch_bounds__(1024) void k_scan(int n) {
    __shared__ int wsum[32];
    __shared__ int s_total;
    __shared__ int s_excl;

    int t = threadIdx.x, lane = t & 31, w = t >> 5;
    int b = blockIdx.x;
    int i = b * 1024 + t;
    int v = (i < n) ? g_indeg[i] : 0;
    int x = v;
    #pragma unroll
    for (int d = 1; d < 32; d <<= 1) {
        int y = __shfl_up_sync(0xffffffffu, x, d);
        if (lane >= d) x += y;
    }
    if (lane == 31) wsum[w] = x;
    __syncthreads();
    if (w == 0) {
        int y = wsum[lane];
        int z = y;
        #pragma unroll
        for (int d = 1; d < 32; d <<= 1) {
            int u = __shfl_up_sync(0xffffffffu, z, d);
            if (lane >= d) z += u;
        }
        wsum[lane] = z - y;  // exclusive warp offsets
    }
    __syncthreads();
    x += wsum[w];            // block-inclusive prefix
    if (t == 1023) s_total = x;
    __syncthreads();

    if (t == 0) {
        int total = s_total;
        // publish: block 0 publishes PREFIX (flag 2), others AGG (flag 1)
        unsigned long long pub = (b == 0)
            ? ((2ull << 32) | (unsigned)total)
            : ((1ull << 32) | (unsigned)total);
        __threadfence();
        atomicExch(&g_state[b], pub);
        int running = 0;
        if (b > 0) {
            int p = b - 1;
            while (true) {
                unsigned long long s = atomicAdd(&g_state[p], 0ull);
                unsigned flag = (unsigned)(s >> 32);
                if (flag == 2u) { running += (int)(unsigned)s; break; }
                if (flag == 1u) { running += (int)(unsigned)s; p--; }
                // flag==0: spin
            }
            __threadfence();
            atomicExch(&g_state[b], (2ull << 32) | (unsigned)(running + s_total));
        }
        s_excl = running;
    }
    __syncthreads();

    if (i < n) {
        g_offs[i] = s_excl + x - v;            // global exclusive prefix
        g_dinv[i] = rsqrtf((float)(v + 1));
        g_indeg[i] = 0;                        // ready for next replay
    }
    __syncthreads();
    if (t == 0) {
        __threadfence();
        int d = atomicAdd(&g_done, 1);
        if (d == (int)gridDim.x - 1) {         // last block: reset lookback state
            for (int k = 0; k < (int)gridDim.x; k++) g_state[k] = 0ull;
            g_done = 0;
            __threadfence();
        }
    }
}

// Scatter src indices; atomicAdd shifts g_offs so post-fill offs[v] = range end.
__global__ void k_fill(const int* __restrict__ src, const int* __restrict__ dst, int E) {
    int i = (blockIdx.x * blockDim.x + threadIdx.x) * 4;
    if (i + 4 <= E) {
        int4 s = __ldg((const int4*)(src + i));
        int4 d = __ldg((const int4*)(dst + i));
        g_csr[atomicAdd(&g_offs[d.x], 1)] = s.x;
        g_csr[atomicAdd(&g_offs[d.y], 1)] = s.y;
        g_csr[atomicAdd(&g_offs[d.z], 1)] = s.z;
        g_csr[atomicAdd(&g_offs[d.w], 1)] = s.w;
    } else {
        for (; i < E; i++) {
            g_csr[atomicAdd(&g_offs[dst[i]], 1)] = src[i];
        }
    }
}

// ---------------------------------------------------------------------------
// GEMM + fused dinv-scale + fp16 store: m[r] = fp16(dinv[r] * (X@W)[r]).
// 128 threads/block, 128 rows/block; 8x8 tile/thread via packed f32x2 FMA.
// ---------------------------------------------------------------------------
__global__ __launch_bounds__(128) void k_gemm64h(const float* __restrict__ X,
                                                 const float* __restrict__ W,
                                                 __half* __restrict__ Yh, int n) {
    __shared__ float Ws[64 * 64];
    __shared__ float Xs[128 * 65];  // pad to 65 to avoid bank conflicts

    int t = threadIdx.x;
    #pragma unroll
    for (int i = t; i < 4096; i += 128) Ws[i] = W[i];

    int row0 = blockIdx.x * 128;
    for (int i = t; i < 8192; i += 128) {
        int r = i >> 6, c = i & 63;
        int gr = row0 + r;
        Xs[r * 65 + c] = (gr < n) ? X[gr * 64 + c] : 0.f;
    }
    __syncthreads();

    int cg = t & 7;       // column group: cols [cg*8, cg*8+8)
    int rg = t >> 3;      // row group:    rows [rg*8, rg*8+8)

    unsigned long long acc[8][4];
    #pragma unroll
    for (int i = 0; i < 8; i++)
        #pragma unroll
        for (int j = 0; j < 4; j++) acc[i][j] = 0ull;

    #pragma unroll 4
    for (int k = 0; k < 64; k++) {
        ulonglong2 wA = *(const ulonglong2*)&Ws[k * 64 + cg * 8];
        ulonglong2 wB = *(const ulonglong2*)&Ws[k * 64 + cg * 8 + 4];
        #pragma unroll
        for (int i = 0; i < 8; i++) {
            unsigned long long xp = pack2(Xs[(rg * 8 + i) * 65 + k]);
            ffma2(acc[i][0], xp, wA.x);
            ffma2(acc[i][1], xp, wA.y);
            ffma2(acc[i][2], xp, wB.x);
            ffma2(acc[i][3], xp, wB.y);
        }
    }

    #pragma unroll
    for (int i = 0; i < 8; i++) {
        int gr = row0 + rg * 8 + i;
        if (gr < n) {
            float dv = __ldg(&g_dinv[gr]);
            float2 p0 = unpack2(acc[i][0]), p1 = unpack2(acc[i][1]);
            float2 p2 = unpack2(acc[i][2]), p3 = unpack2(acc[i][3]);
            uint4 pk;
            pk.x = h2_bits(__floats2half2_rn(p0.x * dv, p0.y * dv));
            pk.y = h2_bits(__floats2half2_rn(p1.x * dv, p1.y * dv));
            pk.z = h2_bits(__floats2half2_rn(p2.x * dv, p2.y * dv));
            pk.w = h2_bits(__floats2half2_rn(p3.x * dv, p3.y * dv));
            *(uint4*)&Yh[gr * 64 + cg * 8] = pk;
        }
    }
}

// ---------------------------------------------------------------------------
// Pull aggregation from pre-scaled fp16 messages:
//   acc = m[v] + sum_e m[csr[e]];  out[v] = relu(dinv[v]*acc + bias)
// One warp per node; lane owns half2 columns [2*lane, 2*lane+1].
// Post-fill offs: begin = offs[v-1] (0 for v=0), end = offs[v].
// ---------------------------------------------------------------------------
__global__ __launch_bounds__(256) void k_agg(const __half2* __restrict__ xwh,
                                             const float* __restrict__ bias,
                                             float* __restrict__ out, int n) {
    int v = (blockIdx.x * 256 + threadIdx.x) >> 5;
    int lane = threadIdx.x & 31;
    if (v >= n) return;
    float dv = g_dinv[v];

    float2 sf = __half22float2(__ldg(&xwh[v * 32 + lane]));
    float ax = sf.x, ay = sf.y;   // self-loop message (scale applied at the end)

    int e = (v == 0) ? 0 : __ldg(&g_offs[v - 1]);
    int end = __ldg(&g_offs[v]);

    // 8-deep MLP batches
    for (; e + 8 <= end; e += 8) {
        int s0 = __ldg(&g_csr[e]);
        int s1 = __ldg(&g_csr[e + 1]);
        int s2 = __ldg(&g_csr[e + 2]);
        int s3 = __ldg(&g_csr[e + 3]);
        int s4 = __ldg(&g_csr[e + 4]);
        int s5 = __ldg(&g_csr[e + 5]);
        int s6 = __ldg(&g_csr[e + 6]);
        int s7 = __ldg(&g_csr[e + 7]);
        float2 m0 = __half22float2(__ldg(&xwh[s0 * 32 + lane]));
        float2 m1 = __half22float2(__ldg(&xwh[s1 * 32 + lane]));
        float2 m2 = __half22float2(__ldg(&xwh[s2 * 32 + lane]));
        float2 m3 = __half22float2(__ldg(&xwh[s3 * 32 + lane]));
        float2 m4 = __half22float2(__ldg(&xwh[s4 * 32 + lane]));
        float2 m5 = __half22float2(__ldg(&xwh[s5 * 32 + lane]));
        float2 m6 = __half22float2(__ldg(&xwh[s6 * 32 + lane]));
        float2 m7 = __half22float2(__ldg(&xwh[s7 * 32 + lane]));
        ax += (m0.x + m1.x) + (m2.x + m3.x) + (m4.x + m5.x) + (m6.x + m7.x);
        ay += (m0.y + m1.y) + (m2.y + m3.y) + (m4.y + m5.y) + (m6.y + m7.y);
    }
    if (e + 4 <= end) {
        int s0 = __ldg(&g_csr[e]);
        int s1 = __ldg(&g_csr[e + 1]);
        int s2 = __ldg(&g_csr[e + 2]);
        int s3 = __ldg(&g_csr[e + 3]);
        float2 m0 = __half22float2(__ldg(&xwh[s0 * 32 + lane]));
        float2 m1 = __half22float2(__ldg(&xwh[s1 * 32 + lane]));
        float2 m2 = __half22float2(__ldg(&xwh[s2 * 32 + lane]));
        float2 m3 = __half22float2(__ldg(&xwh[s3 * 32 + lane]));
        ax += (m0.x + m1.x) + (m2.x + m3.x);
        ay += (m0.y + m1.y) + (m2.y + m3.y);
        e += 4;
    }
    for (; e < end; e++) {
        int s = __ldg(&g_csr[e]);
        float2 m = __half22float2(__ldg(&xwh[s * 32 + lane]));
        ax += m.x;
        ay += m.y;
    }

    float bx = __ldg(&bias[lane * 2]), by = __ldg(&bias[lane * 2 + 1]);
    float2 r;
    r.x = fmaxf(fmaf(ax, dv, bx), 0.f);
    r.y = fmaxf(fmaf(ay, dv, by), 0.f);
    ((float2*)out)[v * 32 + lane] = r;
}

// ---------------------------------------------------------------------------
extern "C" void kernel_launch(void* const* d_in, const int* in_sizes, int n_in,
                              void* d_out, int out_size) {
    const float* x  = (const float*)d_in[0];
    const int*   ei = (const int*)d_in[1];
    const float* W1 = (const float*)d_in[2];
    const float* b1 = (const float*)d_in[3];
    const float* W2 = (const float*)d_in[4];
    const float* b2 = (const float*)d_in[5];
    float* out = (float*)d_out;

    int N = in_sizes[0] / 64;
    int E = in_sizes[1] / 2;
    const int* src = ei;
    const int* dst = ei + E;
    int E4 = E / 4;

    int nbE4 = (E4 + 255) / 256;
    int nbScan = (N + 1023) / 1024;
    int nbAgg = (N + 7) / 8;       // 8 warps per 256-thread block
    int nbGemm = (N + 127) / 128;

    __half* hbuf;   cudaGetSymbolAddress((void**)&hbuf, g_hbuf);
    float* bufB;    cudaGetSymbolAddress((void**)&bufB, g_bufB);

    // CSR build: 2 launches (hist + single-pass lookback scan)
    k_hist<<<nbE4, 256>>>((const int4*)dst, E4, dst, E);
    k_scan<<<nbScan, 1024>>>(N);

    // Layer 1
    k_gemm64h<<<nbGemm, 128>>>(x, W1, hbuf, N);
    k_fill<<<nbE4, 256>>>(src, dst, E);
    k_agg<<<nbAgg, 256>>>((const __half2*)hbuf, b1, bufB, N);

    // Layer 2
    k_gemm64h<<<nbGemm, 128>>>(bufB, W2, hbuf, N);
    k_agg<<<nbAgg, 256>>>((const __half2*)hbuf, b2, out, N);
}

// round 7
// speedup vs baseline: 1.0778x; 1.0778x over previous
#include <cuda_runtime.h>
#include <cuda_fp16.h>

// Fixed problem shape (SimpleGNN): N=100000 nodes, E=1600000 edges, dims 64->64->64
#define MAXN 100000
#define MAXE 1600000

// Scratch (device globals -- no runtime allocation allowed)
__device__ __half g_hbuf[MAXN * 64];   // fp16 pre-scaled message table
__device__ float  g_bufB[MAXN * 64];   // fp32 hidden activations
__device__ int    g_indeg[MAXN];
__device__ int    g_incl[MAXN];
__device__ int    g_offs[MAXN + 1];    // exclusive offsets (immutable after scan3)
__device__ int    g_rank[MAXE];        // within-node rank of each edge (from hist)
__device__ int    g_csr[MAXE];         // src index only (weight folded into message)
__device__ float  g_dinv[MAXN];
__device__ int    g_bsums[128];

// ---------------------------------------------------------------------------
// f32x2 packed-FMA helpers (sm_10x FFMA2 -- only reachable via PTX)
// ---------------------------------------------------------------------------
__device__ __forceinline__ void ffma2(unsigned long long& acc,
                                      unsigned long long a, unsigned long long b) {
    asm("fma.rn.f32x2 %0, %1, %2, %0;" : "+l"(acc) : "l"(a), "l"(b));
}
__device__ __forceinline__ unsigned long long pack2(float v) {
    unsigned long long r;
    asm("mov.b64 %0, {%1, %1};" : "=l"(r) : "f"(v));
    return r;
}
__device__ __forceinline__ float2 unpack2(unsigned long long v) {
    float2 r;
    asm("mov.b64 {%0, %1}, %2;" : "=f"(r.x), "=f"(r.y) : "l"(v));
    return r;
}
__device__ __forceinline__ unsigned h2_bits(__half2 h) {
    return *reinterpret_cast<unsigned*>(&h);
}

// ---------------------------------------------------------------------------
// Histogram of in-degrees + per-edge rank (position within its node's segment)
// ---------------------------------------------------------------------------
__global__ void k_hist(const int* __restrict__ dst, int E) {
    int i = (blockIdx.x * blockDim.x + threadIdx.x) * 4;
    if (i + 4 <= E) {
        int4 d = __ldg((const int4*)(dst + i));
        int4 r;
        r.x = atomicAdd(&g_indeg[d.x], 1);
        r.y = atomicAdd(&g_indeg[d.y], 1);
        r.z = atomicAdd(&g_indeg[d.z], 1);
        r.w = atomicAdd(&g_indeg[d.w], 1);
        *(int4*)(g_rank + i) = r;
    } else {
        for (; i < E; i++) g_rank[i] = atomicAdd(&g_indeg[dst[i]], 1);
    }
}

// dinv = rsqrt(indeg+1); only needs hist. Runs on the side stream before GEMM1.
__global__ void k_dinv(int n) {
    int i = blockIdx.x * blockDim.x + threadIdx.x;
    if (i < n) g_dinv[i] = rsqrtf((float)(g_indeg[i] + 1));
}

// Inclusive scan of indeg per 1024-block (shfl-based); block totals to g_bsums.
__global__ void k_scan1(int n) {
    __shared__ int wsum[32];
    int t = threadIdx.x, lane = t & 31, w = t >> 5;
    int i = blockIdx.x * 1024 + t;
    int v = (i < n) ? g_indeg[i] : 0;
    int x = v;
    #pragma unroll
    for (int d = 1; d < 32; d <<= 1) {
        int y = __shfl_up_sync(0xffffffffu, x, d);
        if (lane >= d) x += y;
    }
    if (lane == 31) wsum[w] = x;
    __syncthreads();
    if (w == 0) {
        int y = wsum[lane];
        int z = y;
        #pragma unroll
        for (int d = 1; d < 32; d <<= 1) {
            int u = __shfl_up_sync(0xffffffffu, z, d);
            if (lane >= d) z += u;
        }
        wsum[lane] = z - y;  // exclusive
    }
    __syncthreads();
    x += wsum[w];
    if (i < n) g_incl[i] = x;
    if (t == 1023) g_bsums[blockIdx.x] = x;
}

// Parallel exclusive scan of <=128 block sums (1 block, 128 threads).
__global__ void k_scan2(int nb) {
    int t = threadIdx.x;
    int lane = t & 31, w = t >> 5;
    int v = (t < nb) ? g_bsums[t] : 0;
    int x = v;
    #pragma unroll
    for (int d = 1; d < 32; d <<= 1) {
        int y = __shfl_up_sync(0xffffffffu, x, d);
        if (lane >= d) x += y;
    }
    __shared__ int wt[4];
    if (lane == 31) wt[w] = x;
    __syncthreads();
    int add = 0;
    for (int k = 0; k < w; k++) add += wt[k];
    x += add;
    if (t < nb) g_bsums[t] = x - v;   // exclusive
}

// Exclusive offsets (+ total at [n]).
__global__ void k_scan3(int n) {
    int i = blockIdx.x * blockDim.x + threadIdx.x;
    if (i < n) {
        int ind = g_indeg[i];
        int base = g_incl[i] + g_bsums[i >> 10];
        g_offs[i] = base - ind;
        if (i == n - 1) g_offs[n] = base;
    }
}

// Atomic-free scatter: pos = offs[dst] + rank (rank precomputed in hist).
__global__ void k_fill(const int* __restrict__ src, const int* __restrict__ dst, int E) {
    int i = (blockIdx.x * blockDim.x + threadIdx.x) * 4;
    if (i + 4 <= E) {
        int4 s = __ldg((const int4*)(src + i));
        int4 d = __ldg((const int4*)(dst + i));
        int4 r = *(const int4*)(g_rank + i);
        int p0 = __ldg(&g_offs[d.x]) + r.x;
        int p1 = __ldg(&g_offs[d.y]) + r.y;
        int p2 = __ldg(&g_offs[d.z]) + r.z;
        int p3 = __ldg(&g_offs[d.w]) + r.w;
        g_csr[p0] = s.x;
        g_csr[p1] = s.y;
        g_csr[p2] = s.z;
        g_csr[p3] = s.w;
    } else {
        for (; i < E; i++) {
            g_csr[__ldg(&g_offs[dst[i]]) + g_rank[i]] = src[i];
        }
    }
}

// ---------------------------------------------------------------------------
// GEMM + fused dinv-scale + fp16 store: m[r] = fp16(dinv[r] * (X@W)[r]).
// 128 threads/block, 128 rows/block; 8x8 tile/thread via packed f32x2 FMA.
// ---------------------------------------------------------------------------
__global__ __launch_bounds__(128) void k_gemm64h(const float* __restrict__ X,
                                                 const float* __restrict__ W,
                                                 __half* __restrict__ Yh, int n) {
    __shared__ float Ws[64 * 64];
    __shared__ float Xs[128 * 65];  // pad to 65 to avoid bank conflicts

    int t = threadIdx.x;
    #pragma unroll
    for (int i = t; i < 4096; i += 128) Ws[i] = W[i];

    int row0 = blockIdx.x * 128;
    for (int i = t; i < 8192; i += 128) {
        int r = i >> 6, c = i & 63;
        int gr = row0 + r;
        Xs[r * 65 + c] = (gr < n) ? X[gr * 64 + c] : 0.f;
    }
    __syncthreads();

    int cg = t & 7;       // column group: cols [cg*8, cg*8+8)
    int rg = t >> 3;      // row group:    rows [rg*8, rg*8+8)

    unsigned long long acc[8][4];
    #pragma unroll
    for (int i = 0; i < 8; i++)
        #pragma unroll
        for (int j = 0; j < 4; j++) acc[i][j] = 0ull;

    #pragma unroll 4
    for (int k = 0; k < 64; k++) {
        ulonglong2 wA = *(const ulonglong2*)&Ws[k * 64 + cg * 8];
        ulonglong2 wB = *(const ulonglong2*)&Ws[k * 64 + cg * 8 + 4];
        #pragma unroll
        for (int i = 0; i < 8; i++) {
            unsigned long long xp = pack2(Xs[(rg * 8 + i) * 65 + k]);
            ffma2(acc[i][0], xp, wA.x);
            ffma2(acc[i][1], xp, wA.y);
            ffma2(acc[i][2], xp, wB.x);
            ffma2(acc[i][3], xp, wB.y);
        }
    }

    #pragma unroll
    for (int i = 0; i < 8; i++) {
        int gr = row0 + rg * 8 + i;
        if (gr < n) {
            float dv = __ldg(&g_dinv[gr]);
            float2 p0 = unpack2(acc[i][0]), p1 = unpack2(acc[i][1]);
            float2 p2 = unpack2(acc[i][2]), p3 = unpack2(acc[i][3]);
            uint4 pk;
            pk.x = h2_bits(__floats2half2_rn(p0.x * dv, p0.y * dv));
            pk.y = h2_bits(__floats2half2_rn(p1.x * dv, p1.y * dv));
            pk.z = h2_bits(__floats2half2_rn(p2.x * dv, p2.y * dv));
            pk.w = h2_bits(__floats2half2_rn(p3.x * dv, p3.y * dv));
            *(uint4*)&Yh[gr * 64 + cg * 8] = pk;
        }
    }
}

// ---------------------------------------------------------------------------
// Pull aggregation from pre-scaled fp16 messages:
//   acc = m[v] + sum_e m[csr[e]];  out[v] = relu(dinv[v]*acc + bias)
// One warp per node; lane owns half2 columns [2*lane, 2*lane+1].
// ---------------------------------------------------------------------------
__global__ __launch_bounds__(256) void k_agg(const __half2* __restrict__ xwh,
                                             const float* __restrict__ bias,
                                             float* __restrict__ out, int n) {
    int v = (blockIdx.x * 256 + threadIdx.x) >> 5;
    int lane = threadIdx.x & 31;
    if (v >= n) return;
    float dv = g_dinv[v];

    float2 sf = __half22float2(__ldg(&xwh[v * 32 + lane]));
    float ax = sf.x, ay = sf.y;   // self-loop message (scale applied at the end)

    int e = __ldg(&g_offs[v]);
    int end = __ldg(&g_offs[v + 1]);

    // 8-deep MLP batches
    for (; e + 8 <= end; e += 8) {
        int s0 = __ldg(&g_csr[e]);
        int s1 = __ldg(&g_csr[e + 1]);
        int s2 = __ldg(&g_csr[e + 2]);
        int s3 = __ldg(&g_csr[e + 3]);
        int s4 = __ldg(&g_csr[e + 4]);
        int s5 = __ldg(&g_csr[e + 5]);
        int s6 = __ldg(&g_csr[e + 6]);
        int s7 = __ldg(&g_csr[e + 7]);
        float2 m0 = __half22float2(__ldg(&xwh[s0 * 32 + lane]));
        float2 m1 = __half22float2(__ldg(&xwh[s1 * 32 + lane]));
        float2 m2 = __half22float2(__ldg(&xwh[s2 * 32 + lane]));
        float2 m3 = __half22float2(__ldg(&xwh[s3 * 32 + lane]));
        float2 m4 = __half22float2(__ldg(&xwh[s4 * 32 + lane]));
        float2 m5 = __half22float2(__ldg(&xwh[s5 * 32 + lane]));
        float2 m6 = __half22float2(__ldg(&xwh[s6 * 32 + lane]));
        float2 m7 = __half22float2(__ldg(&xwh[s7 * 32 + lane]));
        ax += (m0.x + m1.x) + (m2.x + m3.x) + (m4.x + m5.x) + (m6.x + m7.x);
        ay += (m0.y + m1.y) + (m2.y + m3.y) + (m4.y + m5.y) + (m6.y + m7.y);
    }
    if (e + 4 <= end) {
        int s0 = __ldg(&g_csr[e]);
        int s1 = __ldg(&g_csr[e + 1]);
        int s2 = __ldg(&g_csr[e + 2]);
        int s3 = __ldg(&g_csr[e + 3]);
        float2 m0 = __half22float2(__ldg(&xwh[s0 * 32 + lane]));
        float2 m1 = __half22float2(__ldg(&xwh[s1 * 32 + lane]));
        float2 m2 = __half22float2(__ldg(&xwh[s2 * 32 + lane]));
        float2 m3 = __half22float2(__ldg(&xwh[s3 * 32 + lane]));
        ax += (m0.x + m1.x) + (m2.x + m3.x);
        ay += (m0.y + m1.y) + (m2.y + m3.y);
        e += 4;
    }
    for (; e < end; e++) {
        int s = __ldg(&g_csr[e]);
        float2 m = __half22float2(__ldg(&xwh[s * 32 + lane]));
        ax += m.x;
        ay += m.y;
    }

    float bx = __ldg(&bias[lane * 2]), by = __ldg(&bias[lane * 2 + 1]);
    float2 r;
    r.x = fmaxf(fmaf(ax, dv, bx), 0.f);
    r.y = fmaxf(fmaf(ay, dv, by), 0.f);
    ((float2*)out)[v * 32 + lane] = r;
}

// ---------------------------------------------------------------------------
extern "C" void kernel_launch(void* const* d_in, const int* in_sizes, int n_in,
                              void* d_out, int out_size) {
    const float* x  = (const float*)d_in[0];
    const int*   ei = (const int*)d_in[1];
    const float* W1 = (const float*)d_in[2];
    const float* b1 = (const float*)d_in[3];
    const float* W2 = (const float*)d_in[4];
    const float* b2 = (const float*)d_in[5];
    float* out = (float*)d_out;

    int N = in_sizes[0] / 64;
    int E = in_sizes[1] / 2;
    const int* src = ei;
    const int* dst = ei + E;
    int E4 = E / 4;

    int nbN = (N + 255) / 256;
    int nbE4 = (E4 + 255) / 256;
    int nbScan = (N + 1023) / 1024;
    int nbAgg = (N + 7) / 8;       // 8 warps per 256-thread block
    int nbGemm = (N + 127) / 128;

    void* indegPtr;  cudaGetSymbolAddress(&indegPtr, g_indeg);
    __half* hbuf;    cudaGetSymbolAddress((void**)&hbuf, g_hbuf);
    float* bufB;     cudaGetSymbolAddress((void**)&bufB, g_bufB);

    // One-time side stream + events (created on the pre-capture correctness
    // call; reused by every call -> identical, deterministic launch pattern).
    static cudaStream_t s1 = nullptr;
    static cudaEvent_t evFork = nullptr, evJoin = nullptr;
    static bool streamsOk = false;
    static bool tried = false;
    if (!tried) {
        tried = true;
        streamsOk = (cudaStreamCreateWithFlags(&s1, cudaStreamNonBlocking) == cudaSuccess) &&
                    (cudaEventCreateWithFlags(&evFork, cudaEventDisableTiming) == cudaSuccess) &&
                    (cudaEventCreateWithFlags(&evJoin, cudaEventDisableTiming) == cudaSuccess);
    }

    // CSR build prologue (default stream)
    cudaMemsetAsync(indegPtr, 0, (size_t)N * sizeof(int));
    k_hist<<<nbE4, 256>>>(dst, E);

    if (streamsOk) {
        // Fork: side stream does dinv + GEMM1 while main does scan+fill.
        cudaEventRecord(evFork, 0);
        cudaStreamWaitEvent(s1, evFork, 0);
        k_dinv<<<nbN, 256, 0, s1>>>(N);
        k_gemm64h<<<nbGemm, 128, 0, s1>>>(x, W1, hbuf, N);
        cudaEventRecord(evJoin, s1);

        k_scan1<<<nbScan, 1024>>>(N);
        k_scan2<<<1, 128>>>(nbScan);
        k_scan3<<<nbN, 256>>>(N);
        k_fill<<<nbE4, 256>>>(src, dst, E);

        cudaStreamWaitEvent(0, evJoin, 0);
    } else {
        k_dinv<<<nbN, 256>>>(N);
        k_gemm64h<<<nbGemm, 128>>>(x, W1, hbuf, N);
        k_scan1<<<nbScan, 1024>>>(N);
        k_scan2<<<1, 128>>>(nbScan);
        k_scan3<<<nbN, 256>>>(N);
        k_fill<<<nbE4, 256>>>(src, dst, E);
    }

    // Layer 1 aggregate, then layer 2
    k_agg<<<nbAgg, 256>>>((const __half2*)hbuf, b1, bufB, N);
    k_gemm64h<<<nbGemm, 128>>>(bufB, W2, hbuf, N);
    k_agg<<<nbAgg, 256>>>((const __half2*)hbuf, b2, out, N);
}